// round 17
// baseline (speedup 1.0000x reference)
#include <cuda_runtime.h>

// ---------------------------------------------------------------------------
// SphericalExpansion:
//  - k_fill filters r >= R_CUT pairs (fc==0 => exact zero) and stores
//    (dx,dy,dz,species) payload per bucket slot.
//  - k_acc: TWO atoms per warp (lanes 0-15 -> atom A pairs, 16-31 -> atom B),
//    16-pair tiles, stride-20 smem rows. Accumulation uses 2x4 per-lane
//    output blocks: LDS.64 (Y pair) + LDS.128 (F quad) + 4x fma.rn.f32x2
//    (FFMA2) per staged row. Self-resets g_count (zero-init at load).
// ---------------------------------------------------------------------------

constexpr int MAX_ATOMS = 20000;
constexpr int CAP       = 96;       // mean filtered count ~16; huge margin
constexpr float R_CUT_F = 5.0f;

__device__ int    g_count[MAX_ATOMS];        // zero-initialized at module load
__device__ float4 g_vec[MAX_ATOMS * CAP];    // (dx,dy,dz, species-as-float)

using u64 = unsigned long long;

__device__ __forceinline__ u64 pack_dup(float a) {
    u64 r;
    asm("mov.b64 %0, {%1, %1};" : "=l"(r) : "f"(a));
    return r;
}
__device__ __forceinline__ void ffma2(u64& acc, u64 a, u64 b) {
    asm("fma.rn.f32x2 %0, %1, %2, %0;" : "+l"(acc) : "l"(a), "l"(b));
}
__device__ __forceinline__ float2 unpack2(u64 v) {
    float2 r;
    asm("mov.b64 {%0, %1}, %2;" : "=f"(r.x), "=f"(r.y) : "l"(v));
    return r;
}

__global__ void k_fill(const float* __restrict__ pos,
                       const int*   __restrict__ centers,
                       const int*   __restrict__ neighbors,
                       const int*   __restrict__ species, int P)
{
    int p = blockIdx.x * blockDim.x + threadIdx.x;
    if (p >= P) return;
    const int c  = centers[p];
    const int nb = neighbors[p];
    const float dx = __ldg(&pos[3 * nb + 0]) - __ldg(&pos[3 * c + 0]);
    const float dy = __ldg(&pos[3 * nb + 1]) - __ldg(&pos[3 * c + 1]);
    const float dz = __ldg(&pos[3 * nb + 2]) - __ldg(&pos[3 * c + 2]);
    const float r2 = dx * dx + dy * dy + dz * dz;
    if (r2 >= R_CUT_F * R_CUT_F) return;      // cosine cutoff -> exact zero
    const int slot = atomicAdd(&g_count[c], 1);
    if (slot < CAP) {
        const int s = __ldg(&species[nb]);
        g_vec[c * CAP + slot] = make_float4(dx, dy, dz, __int_as_float(s));
    }
}

__global__ __launch_bounds__(256) void k_acc(
    const float* __restrict__ W,     // [2,4] row-major
    float*       __restrict__ out,   // [nAtoms, 16, 16]
    int nAtoms)
{
    // stride 20 floats: 16B-aligned rows, conflict-free lane-major writes.
    __shared__ __align__(16) float sY[8][32][20];
    __shared__ __align__(16) float sF[8][32][20];
    __shared__ float sW[8];

    if (threadIdx.x < 8) sW[threadIdx.x] = W[threadIdx.x];
    __syncthreads();

    const int w    = threadIdx.x >> 5;
    const int lane = threadIdx.x & 31;

    const int atomA = blockIdx.x * 16 + w * 2;   // two atoms per warp
    const int atomB = atomA + 1;
    if (atomA >= nAtoms) return;
    const bool hasB = (atomB < nAtoms);

    int cntA = g_count[atomA];
    int cntB = hasB ? g_count[atomB] : 0;
    if (lane == 0) g_count[atomA] = 0;           // self-reset for next launch
    if (lane == 1 && hasB) g_count[atomB] = 0;
    if (cntA > CAP) cntA = CAP;
    if (cntB > CAP) cntB = CAP;

    const int  half   = lane >> 4;               // 0 -> A pairs, 1 -> B pairs
    const int  hl     = lane & 15;
    const int  myAtom = half ? atomB : atomA;
    const int  myCnt  = half ? cntB : cntA;

    // 2x4 ownership: comps {2cg, 2cg+1} x cols {4fg..4fg+3}
    const int cg = lane >> 2;        // 0..7
    const int fg = lane & 3;         // 0..3

    // packed accumulators: [c0 cols01, c0 cols23, c1 cols01, c1 cols23]
    u64 accA[4] = {0ull, 0ull, 0ull, 0ull};
    u64 accB[4] = {0ull, 0ull, 0ull, 0ull};

    // Radial recurrence: rad_n = G * E^n * K1^(n^2)
    const float K1 = __expf(-0.6530612244897959f);   // exp(-(32/49))
    const float K2 = K1 * K1;

    const int tiles = max((cntA + 15) >> 4, (cntB + 15) >> 4);

    for (int t = 0; t < tiles; t++) {
        const int base = t << 4;
        int mA = cntA - base; mA = mA < 0 ? 0 : (mA > 16 ? 16 : mA);
        int mB = cntB - base; mB = mB < 0 ? 0 : (mB > 16 ? 16 : mB);
        const int mrA = (mA + 7) & ~7;
        const int mrB = (mB + 7) & ~7;

        const int k = base + hl;
        if (k < myCnt) {
            float Y[16], F[16];
            const float4 v = __ldg(&g_vec[myAtom * CAP + k]);
            const float r2   = v.x * v.x + v.y * v.y + v.z * v.z + 1e-12f;
            const float rinv = rsqrtf(r2);
            const float r    = r2 * rinv;
            const float x = v.x * rinv, y = v.y * rinv, z = v.z * rinv;
            const float x2 = x * x, y2 = y * y, z2 = z * z;

            Y[0]  = 0.28209479177387814f;
            Y[1]  = 0.4886025119029199f * y;
            Y[2]  = 0.4886025119029199f * z;
            Y[3]  = 0.4886025119029199f * x;
            Y[4]  = 1.0925484305920792f * x * y;
            Y[5]  = 1.0925484305920792f * y * z;
            Y[6]  = 0.31539156525252005f * (3.0f * z2 - 1.0f);
            Y[7]  = 1.0925484305920792f * x * z;
            Y[8]  = 0.5462742152960396f * (x2 - y2);
            Y[9]  = 0.5900435899266435f * y * (3.0f * x2 - y2);
            Y[10] = 2.890611442640554f  * x * y * z;
            Y[11] = 0.4570457994644658f * y * (5.0f * z2 - 1.0f);
            Y[12] = 0.3731763325901154f * z * (5.0f * z2 - 3.0f);
            Y[13] = 0.4570457994644658f * x * (5.0f * z2 - 1.0f);
            Y[14] = 1.445305721320277f  * z * (x2 - y2);
            Y[15] = 0.5900435899266435f * x * (x2 - 3.0f * y2);

            // r < R_CUT guaranteed by k_fill filter
            const float fc = 0.5f * (__cosf(0.6283185307179586f * r) + 1.0f);

            const int   s  = __float_as_int(v.w);
            const float b0 = fc * sW[s];
            const float b1 = fc * sW[4 + s];

            float rad = __expf(-1.28f * r * r);                  // G
            float u   = __expf(1.8285714285714286f * r) * K1;    // E*K1
#pragma unroll
            for (int n = 0; n < 8; n++) {
                F[n]     = b0 * rad;
                F[8 + n] = b1 * rad;
                rad *= u;
                u   *= K2;
            }

#pragma unroll
            for (int j = 0; j < 4; j++) {
                *(float4*)&sY[w][lane][4*j] = make_float4(Y[4*j], Y[4*j+1], Y[4*j+2], Y[4*j+3]);
                *(float4*)&sF[w][lane][4*j] = make_float4(F[4*j], F[4*j+1], F[4*j+2], F[4*j+3]);
            }
        } else if (hl < (half ? mrB : mrA)) {
            // pad rows the 8-unrolled accumulator reads: finite zeros
            const float4 z4 = make_float4(0.f, 0.f, 0.f, 0.f);
#pragma unroll
            for (int j = 0; j < 4; j++) {
                *(float4*)&sY[w][lane][4*j] = z4;
                *(float4*)&sF[w][lane][4*j] = z4;
            }
        }
        __syncwarp();

        // all 32 lanes accumulate atom A over rows [0, mrA)
        for (int p0 = 0; p0 < mrA; p0 += 8) {
#pragma unroll
            for (int pp = 0; pp < 8; pp++) {
                const int p = p0 + pp;
                const float2 y2 = *(const float2*)&sY[w][p][2 * cg];     // LDS.64
                const ulonglong2 f = *(const ulonglong2*)&sF[w][p][4 * fg]; // LDS.128
                const u64 yy0 = pack_dup(y2.x);
                const u64 yy1 = pack_dup(y2.y);
                ffma2(accA[0], yy0, f.x);
                ffma2(accA[1], yy0, f.y);
                ffma2(accA[2], yy1, f.x);
                ffma2(accA[3], yy1, f.y);
            }
        }
        // all 32 lanes accumulate atom B over rows [16, 16+mrB)
        for (int p0 = 0; p0 < mrB; p0 += 8) {
#pragma unroll
            for (int pp = 0; pp < 8; pp++) {
                const int p = 16 + p0 + pp;
                const float2 y2 = *(const float2*)&sY[w][p][2 * cg];
                const ulonglong2 f = *(const ulonglong2*)&sF[w][p][4 * fg];
                const u64 yy0 = pack_dup(y2.x);
                const u64 yy1 = pack_dup(y2.y);
                ffma2(accB[0], yy0, f.x);
                ffma2(accB[1], yy0, f.y);
                ffma2(accB[2], yy1, f.x);
                ffma2(accB[3], yy1, f.y);
            }
        }
        __syncwarp();
    }

    // Epilogue: lane writes comps {2cg,2cg+1} x cols {4fg..4fg+3} per atom.
    {
        const size_t baseA = (size_t)atomA * 256 + (2 * cg) * 16 + 4 * fg;
        const float2 a0 = unpack2(accA[0]), a1 = unpack2(accA[1]);
        const float2 a2 = unpack2(accA[2]), a3 = unpack2(accA[3]);
        *(float4*)(out + baseA)      = make_float4(a0.x, a0.y, a1.x, a1.y);
        *(float4*)(out + baseA + 16) = make_float4(a2.x, a2.y, a3.x, a3.y);
        if (hasB) {
            const size_t baseB = (size_t)atomB * 256 + (2 * cg) * 16 + 4 * fg;
            const float2 b0 = unpack2(accB[0]), b1 = unpack2(accB[1]);
            const float2 b2 = unpack2(accB[2]), b3 = unpack2(accB[3]);
            *(float4*)(out + baseB)      = make_float4(b0.x, b0.y, b1.x, b1.y);
            *(float4*)(out + baseB + 16) = make_float4(b2.x, b2.y, b3.x, b3.y);
        }
    }
}

extern "C" void kernel_launch(void* const* d_in, const int* in_sizes, int n_in,
                              void* d_out, int out_size) {
    const float* pos       = (const float*)d_in[0];
    const float* W         = (const float*)d_in[1];
    const int*   centers   = (const int*)d_in[2];
    const int*   neighbors = (const int*)d_in[3];
    const int*   species   = (const int*)d_in[4];
    float*       out       = (float*)d_out;

    const int P      = in_sizes[2];
    const int nAtoms = in_sizes[4];

    k_fill<<<(P + 255) / 256, 256>>>(pos, centers, neighbors, species, P);
    k_acc<<<(nAtoms + 15) / 16, 256>>>(W, out, nAtoms);
}